// round 2
// baseline (speedup 1.0000x reference)
#include <cuda_runtime.h>
#include <cuda_bf16.h>

// Problem constants
#define NI 64
#define NO 64
#define NN 1024
#define NB 16384
#define NWARM 25
#define JCOLS 960   // columns 64..1023

// ---------------- device scratch (no allocations allowed) ----------------
__device__ float g_ST[NN * NN];       // S transposed: g_ST[j*1024 + k] = sig_diff[k][j]
__device__ float g_W[NI * JCOLS];     // (delta/N) * sig_diff[k][64+jrel], k<64
__device__ float g_colsum0[NN];       // sum_{k<64} sig_diff[k][j]
__device__ float g_buf[2][NN];        // ping-pong unnormalized "new" vectors
__device__ float g_s[NWARM + 2];      // per-iteration normalization sums
__device__ float g_c[JCOLS];          // bias c[jrel] for batch step
__device__ unsigned g_barcnt;
__device__ unsigned g_bargen;

// ---------------- grid barrier (all blocks co-resident: grid <= 120) -----
__device__ __forceinline__ void gridbar(unsigned nb) {
    __threadfence();
    __syncthreads();
    if (threadIdx.x == 0) {
        unsigned g = *(volatile unsigned*)&g_bargen;
        unsigned prev = atomicAdd(&g_barcnt, 1u);
        if (prev == nb - 1u) {
            g_barcnt = 0u;
            __threadfence();
            *(volatile unsigned*)&g_bargen = g + 1u;
        } else {
            while (*(volatile unsigned*)&g_bargen == g) { __nanosleep(64); }
        }
    }
    __syncthreads();
}

// ---------------- kernel A: signatures + init ----------------------------
// grid = 1024 blocks (one per column j), 256 threads
__global__ void kprep(const float* __restrict__ ident,
                      const float* __restrict__ enh,
                      const float* __restrict__ inh,
                      const float* __restrict__ beta,
                      const float* __restrict__ delta) {
    int j = blockIdx.x;
    float b  = beta[0];
    float sc = delta[0] * (1.0f / (float)NN);
    float idj = ident[j];
    __shared__ float red[64];
    for (int k = threadIdx.x; k < NN; k += 256) {
        float v;
        if (k >= NI && k < NI + NO) {
            v = 0.0f;  // masked rows
        } else {
            float e = expf(-b * fabsf(enh[k] - idj));
            float h = expf(-b * fabsf(inh[k] - idj));
            v = e - h;
        }
        g_ST[j * NN + k] = v;
        if (k < NI) {
            red[k] = v;
            if (j >= NI) g_W[k * JCOLS + (j - NI)] = v * sc;
        }
    }
    __syncthreads();
    if (threadIdx.x == 0) {
        float s0 = 0.0f;
        #pragma unroll
        for (int k = 0; k < NI; k++) s0 += red[k];
        g_colsum0[j] = s0;
        g_buf[0][j] = 1.0f / (float)NN;   // conc0
        if (j == 0) {
            g_s[0] = 1.0f;
            for (int t = 1; t < NWARM + 2; t++) g_s[t] = 0.0f;
            g_barcnt = 0u;
            g_bargen = 0u;
        }
    }
}

// ---------------- kernel B: 25 warmup iterations + bias, persistent ------
// grid = 120 blocks x 256 threads; warp w of block b owns column jrel = 8b+w
__global__ void kwarm(const float* __restrict__ delta) {
    const int warp = threadIdx.x >> 5;
    const int lane = threadIdx.x & 31;
    const int jrel = blockIdx.x * 8 + warp;     // 0..959
    const int j = NI + jrel;
    const float dscale = delta[0] * (1.0f / (float)NN);
    const float* STrow = &g_ST[j * NN];
    const float cs0 = g_colsum0[j] * (1.0f / (float)NN);  // const contribution (conc[<64]=1/N)
    __shared__ float bsum[8];

    for (int t = 0; t < NWARM; t++) {
        const float* bp = g_buf[t & 1];
        float s = __ldcg(&g_s[t]);
        float inv = (s > 0.0f) ? (1.0f / s) : 1.0f;
        float acc = 0.0f;
        #pragma unroll
        for (int kk = 128 + lane; kk < NN; kk += 32)
            acc += __ldcg(&bp[kk]) * __ldg(&STrow[kk]);
        #pragma unroll
        for (int o = 16; o > 0; o >>= 1)
            acc += __shfl_xor_sync(0xffffffffu, acc, o);
        if (lane == 0) {
            float dc = dscale * (cs0 + inv * acc);
            float nv = fmaxf(__ldcg(&bp[j]) * inv + dc, 0.0f);
            g_buf[(t + 1) & 1][j] = nv;
            bsum[warp] = nv;
        }
        __syncthreads();
        if (threadIdx.x == 0) {
            float p = 0.0f;
            #pragma unroll
            for (int w = 0; w < 8; w++) p += bsum[w];
            atomicAdd(&g_s[t + 1], p);
        }
        gridbar(120);
    }

    // bias pass: c[jrel] = conc_warm[j] + (delta/N) * sum_{k>=128} conc_warm[k]*S[k][j]
    {
        const float* bp = g_buf[NWARM & 1];
        float s = __ldcg(&g_s[NWARM]);
        float inv = (s > 0.0f) ? (1.0f / s) : 1.0f;
        float acc = 0.0f;
        #pragma unroll
        for (int kk = 128 + lane; kk < NN; kk += 32)
            acc += __ldcg(&bp[kk]) * __ldg(&STrow[kk]);
        #pragma unroll
        for (int o = 16; o > 0; o >>= 1)
            acc += __shfl_xor_sync(0xffffffffu, acc, o);
        if (lane == 0)
            g_c[jrel] = __ldcg(&bp[j]) * inv + dscale * (inv * acc);
    }
}

// ---------------- kernel C: main batch GEMM + relu + rowsum + normalize --
// C[16384 x 960] = X[16384 x 64] * W[64 x 960] + c; relu; rowsum; out = cols 0..63 / s
// Block: 64 rows x all 960 cols (15 chunks of 64). 256 threads, 4x4 microtile,
// row-paired f32x2 accumulation (FFMA2).
#define SMSTRIDE 68

__global__ void __launch_bounds__(256) kmain(const float* __restrict__ X,
                                             float* __restrict__ out) {
    __shared__ __align__(16) float Xs[64 * SMSTRIDE];   // [k][m]
    __shared__ __align__(16) float Ws[64 * SMSTRIDE];   // [k][n]
    const int tid = threadIdx.x;
    const int b0 = blockIdx.x * 64;

    // Load X tile (64 rows x 64 k), transposed into Xs[k][m]
    #pragma unroll
    for (int p = 0; p < 4; p++) {
        int idx = tid + p * 256;          // 0..1023
        int m = idx >> 4, q = idx & 15;
        float4 v = *(const float4*)&X[(b0 + m) * NI + q * 4];
        Xs[(4 * q + 0) * SMSTRIDE + m] = v.x;
        Xs[(4 * q + 1) * SMSTRIDE + m] = v.y;
        Xs[(4 * q + 2) * SMSTRIDE + m] = v.z;
        Xs[(4 * q + 3) * SMSTRIDE + m] = v.w;
    }
    // Load W chunk 0
    #pragma unroll
    for (int p = 0; p < 4; p++) {
        int idx = tid + p * 256;
        int k = idx >> 4, q = idx & 15;
        *(float4*)&Ws[k * SMSTRIDE + 4 * q] = *(const float4*)&g_W[k * JCOLS + 4 * q];
    }
    __syncthreads();

    const int tx = tid & 15, ty = tid >> 4;
    float rs[4] = {0.f, 0.f, 0.f, 0.f};
    float yout[4][4];

    for (int ch = 0; ch < 15; ch++) {
        // prefetch next W chunk into registers (hidden under compute)
        float4 pref[4];
        if (ch < 14) {
            #pragma unroll
            for (int p = 0; p < 4; p++) {
                int idx = tid + p * 256;
                int k = idx >> 4, q = idx & 15;
                pref[p] = *(const float4*)&g_W[k * JCOLS + (ch + 1) * 64 + 4 * q];
            }
        }
        // init accumulators with bias c[j] (both f32x2 lanes = same column)
        unsigned long long acc[2][4];
        #pragma unroll
        for (int ci = 0; ci < 4; ci++) {
            float cj = __ldg(&g_c[ch * 64 + 4 * tx + ci]);
            unsigned long long d;
            asm("mov.b64 %0, {%1, %1};" : "=l"(d) : "f"(cj));
            acc[0][ci] = d;
            acc[1][ci] = d;
        }
        #pragma unroll
        for (int k = 0; k < 64; k++) {
            ulonglong2 a2 = *(ulonglong2*)&Xs[k * SMSTRIDE + 4 * ty];  // rows {m0,m1},{m2,m3}
            float4 bv = *(float4*)&Ws[k * SMSTRIDE + 4 * tx];
            unsigned long long bb;
            #define FMA2STEP(ci, bf)                                                      \
                asm("mov.b64 %0, {%1, %1};" : "=l"(bb) : "f"(bf));                        \
                asm("fma.rn.f32x2 %0, %1, %2, %0;" : "+l"(acc[0][ci]) : "l"(a2.x), "l"(bb)); \
                asm("fma.rn.f32x2 %0, %1, %2, %0;" : "+l"(acc[1][ci]) : "l"(a2.y), "l"(bb));
            FMA2STEP(0, bv.x)
            FMA2STEP(1, bv.y)
            FMA2STEP(2, bv.z)
            FMA2STEP(3, bv.w)
            #undef FMA2STEP
        }
        // epilogue: relu + rowsum (+ stash output chunk)
        #pragma unroll
        for (int p = 0; p < 2; p++) {
            #pragma unroll
            for (int ci = 0; ci < 4; ci++) {
                float2 f = *(float2*)&acc[p][ci];
                float y0 = fmaxf(f.x, 0.0f);
                float y1 = fmaxf(f.y, 0.0f);
                rs[2 * p + 0] += y0;
                rs[2 * p + 1] += y1;
                if (ch == 0) {
                    yout[2 * p + 0][ci] = y0;
                    yout[2 * p + 1][ci] = y1;
                }
            }
        }
        if (ch < 14) {
            __syncthreads();
            #pragma unroll
            for (int p = 0; p < 4; p++) {
                int idx = tid + p * 256;
                int k = idx >> 4, q = idx & 15;
                *(float4*)&Ws[k * SMSTRIDE + 4 * q] = pref[p];
            }
            __syncthreads();
        }
    }

    // reduce row sums across the 16 tx lanes (xor<16 stays within half-warp = same ty)
    #pragma unroll
    for (int r = 0; r < 4; r++) {
        #pragma unroll
        for (int o = 1; o < 16; o <<= 1)
            rs[r] += __shfl_xor_sync(0xffffffffu, rs[r], o);
    }
    // normalize + store output (cols 0..63 == global j 64..127)
    #pragma unroll
    for (int r = 0; r < 4; r++) {
        float s = rs[r];
        float inv = (s > 0.0f) ? (1.0f / s) : 1.0f;
        float4 o4 = make_float4(yout[r][0] * inv, yout[r][1] * inv,
                                yout[r][2] * inv, yout[r][3] * inv);
        *(float4*)&out[(b0 + 4 * ty + r) * NO + 4 * tx] = o4;
    }
}

// ---------------- launch ---------------------------------------------------
extern "C" void kernel_launch(void* const* d_in, const int* in_sizes, int n_in,
                              void* d_out, int out_size) {
    const float* X     = (const float*)d_in[0];  // (16384, 64)
    const float* ident = (const float*)d_in[1];  // (1024,)
    const float* enh   = (const float*)d_in[2];  // (1024,)
    const float* inh   = (const float*)d_in[3];  // (1024,)
    const float* beta  = (const float*)d_in[4];  // (1,)
    const float* delta = (const float*)d_in[5];  // (1,)
    (void)in_sizes; (void)n_in; (void)out_size;

    kprep<<<NN, 256>>>(ident, enh, inh, beta, delta);
    kwarm<<<120, 256>>>(delta);
    kmain<<<NB / 64, 256>>>(X, (float*)d_out);
}

// round 3
// speedup vs baseline: 1.4287x; 1.4287x over previous
#include <cuda_runtime.h>
#include <cuda_bf16.h>

// Problem constants
#define NI 64
#define NO 64
#define NN 1024
#define NB 16384
#define NWARM 25
#define JCOLS 960   // columns 64..1023
#define WBLK 60     // kwarm blocks (co-resident, << 148 SMs)

// ---------------- device scratch (no allocations allowed) ----------------
__device__ float g_ST[NN * NN];       // g_ST[j*1024 + k] = sig_diff[k][j] (rows j>=64 used)
__device__ float g_W[NI * JCOLS];     // (delta/N) * sig_diff[k][64+n], k<64
__device__ float g_colsum0[NN];       // sum_{k<64} sig_diff[k][j]
__device__ float g_buf[2][NN];        // ping-pong unnormalized "new" vectors
__device__ float g_s[NWARM + 2];      // per-iteration normalization sums
__device__ float g_c[JCOLS];          // bias c[n] for batch step
__device__ unsigned g_barcnt;         // monotonic barrier counter

__device__ __forceinline__ unsigned ld_relaxed_gpu(const unsigned* p) {
    unsigned v;
    asm volatile("ld.global.relaxed.gpu.u32 %0, [%1];" : "=r"(v) : "l"(p));
    return v;
}

// ---------------- kernel A: signatures + init ----------------------------
// grid = 960 blocks (one per column j = 64 + bid), 256 threads
__global__ void kprep(const float* __restrict__ ident,
                      const float* __restrict__ enh,
                      const float* __restrict__ inh,
                      const float* __restrict__ beta,
                      const float* __restrict__ delta) {
    int j = NI + blockIdx.x;
    float b  = beta[0];
    float sc = delta[0] * (1.0f / (float)NN);
    float idj = ident[j];
    __shared__ float red[64];
    for (int k = threadIdx.x; k < NN; k += 256) {
        float v;
        if (k >= NI && k < NI + NO) {
            v = 0.0f;  // masked rows
        } else {
            float e = __expf(-b * fabsf(enh[k] - idj));
            float h = __expf(-b * fabsf(inh[k] - idj));
            v = e - h;
        }
        g_ST[j * NN + k] = v;
        if (k < NI) {
            red[k] = v;
            g_W[k * JCOLS + (j - NI)] = v * sc;
        }
    }
    __syncthreads();
    if (threadIdx.x == 0) {
        float s0 = 0.0f;
        #pragma unroll
        for (int k = 0; k < NI; k++) s0 += red[k];
        g_colsum0[j] = s0;
        g_buf[0][j] = 1.0f / (float)NN;   // conc0 (reg part)
        if (j == NI) {
            g_s[0] = 1.0f;
            for (int t = 1; t < NWARM + 2; t++) g_s[t] = 0.0f;
            g_barcnt = 0u;
        }
    }
}

// ---------------- kernel B: 25 warmup iterations + bias, persistent ------
// grid = 60 blocks x 512 threads; warp w of block b owns column jrel = 16b+w
__global__ void __launch_bounds__(512) kwarm(const float* __restrict__ delta) {
    const int warp = threadIdx.x >> 5;
    const int lane = threadIdx.x & 31;
    const int jrel = blockIdx.x * 16 + warp;     // 0..959
    const int j = NI + jrel;
    const float dscale = delta[0] * (1.0f / (float)NN);
    const float cs0 = g_colsum0[j] * (1.0f / (float)NN);
    __shared__ float bsum[16];

    // Cache this warp's slice of S^T (k = 128 + lane + 32*i) in registers.
    float st[28];
    #pragma unroll
    for (int i = 0; i < 28; i++)
        st[i] = __ldg(&g_ST[j * NN + 128 + lane + 32 * i]);

    for (int t = 0; t < NWARM; t++) {
        const float* bp = g_buf[t & 1];
        float s = __ldcg(&g_s[t]);
        float inv = (s > 0.0f) ? (1.0f / s) : 1.0f;
        float a0 = 0.f, a1 = 0.f, a2 = 0.f, a3 = 0.f;
        #pragma unroll
        for (int i = 0; i < 28; i += 4) {
            a0 += __ldcg(&bp[128 + lane + 32 * (i + 0)]) * st[i + 0];
            a1 += __ldcg(&bp[128 + lane + 32 * (i + 1)]) * st[i + 1];
            a2 += __ldcg(&bp[128 + lane + 32 * (i + 2)]) * st[i + 2];
            a3 += __ldcg(&bp[128 + lane + 32 * (i + 3)]) * st[i + 3];
        }
        float acc = (a0 + a1) + (a2 + a3);
        #pragma unroll
        for (int o = 16; o > 0; o >>= 1)
            acc += __shfl_xor_sync(0xffffffffu, acc, o);
        if (lane == 0) {
            float nv = fmaxf(__ldcg(&bp[j]) * inv + dscale * (cs0 + inv * acc), 0.0f);
            g_buf[(t + 1) & 1][j] = nv;
            bsum[warp] = nv;
        }
        __syncthreads();
        if (threadIdx.x == 0) {
            float p = 0.0f;
            #pragma unroll
            for (int w = 0; w < 16; w++) p += bsum[w];
            atomicAdd(&g_s[t + 1], p);
            asm volatile("fence.acq_rel.gpu;" ::: "memory");   // release block's writes
            atomicAdd(&g_barcnt, 1u);
            unsigned tgt = (unsigned)WBLK * (unsigned)(t + 1);
            while (ld_relaxed_gpu(&g_barcnt) < tgt) { }
            asm volatile("fence.acq_rel.gpu;" ::: "memory");   // acquire others' writes
        }
        __syncthreads();
    }

    // bias pass: c[n] = conc_warm[j] + (delta/N) * sum_{k>=128} conc_warm[k]*S[k][j]
    {
        const float* bp = g_buf[NWARM & 1];
        float s = __ldcg(&g_s[NWARM]);
        float inv = (s > 0.0f) ? (1.0f / s) : 1.0f;
        float a0 = 0.f, a1 = 0.f, a2 = 0.f, a3 = 0.f;
        #pragma unroll
        for (int i = 0; i < 28; i += 4) {
            a0 += __ldcg(&bp[128 + lane + 32 * (i + 0)]) * st[i + 0];
            a1 += __ldcg(&bp[128 + lane + 32 * (i + 1)]) * st[i + 1];
            a2 += __ldcg(&bp[128 + lane + 32 * (i + 2)]) * st[i + 2];
            a3 += __ldcg(&bp[128 + lane + 32 * (i + 3)]) * st[i + 3];
        }
        float acc = (a0 + a1) + (a2 + a3);
        #pragma unroll
        for (int o = 16; o > 0; o >>= 1)
            acc += __shfl_xor_sync(0xffffffffu, acc, o);
        if (lane == 0)
            g_c[jrel] = __ldcg(&bp[j]) * inv + dscale * (inv * acc);
    }
}

// ---------------- kernel C: main batch GEMM + relu + rowsum + normalize --
// C[16384 x 960] = X[16384 x 64] * W[64 x 960] + c; relu; rowsum; out = cols 0..63 / s
// 64 rows/block, 15 col-chunks of 64. 256 threads, 4 rows x 4 cols per thread.
// f32x2 accumulators paired over COLUMNS: b pairs are free (reinterpret natural
// float4 from Ws); a is read pre-duplicated from Xsdup. 0 MOVs per k.
__global__ void __launch_bounds__(256) kmain(const float* __restrict__ X,
                                             float* __restrict__ out) {
    __shared__ __align__(16) float Xsdup[64 * 128];  // [k][2*m] duplicated pairs (32KB)
    __shared__ __align__(16) float Ws[64 * 64];      // [k][n] natural (16KB)
    const int tid = threadIdx.x;
    const int b0 = blockIdx.x * 64;

    // Load X tile, transposed + duplicated into Xsdup[k][2m] = {x,x}
    #pragma unroll
    for (int p = 0; p < 4; p++) {
        int idx = tid + p * 256;          // 0..1023
        int m = idx >> 4, q = idx & 15;
        float4 v = *(const float4*)&X[(b0 + m) * NI + q * 4];
        *(float2*)&Xsdup[(4 * q + 0) * 128 + 2 * m] = make_float2(v.x, v.x);
        *(float2*)&Xsdup[(4 * q + 1) * 128 + 2 * m] = make_float2(v.y, v.y);
        *(float2*)&Xsdup[(4 * q + 2) * 128 + 2 * m] = make_float2(v.z, v.z);
        *(float2*)&Xsdup[(4 * q + 3) * 128 + 2 * m] = make_float2(v.w, v.w);
    }
    // Load W chunk 0
    #pragma unroll
    for (int p = 0; p < 4; p++) {
        int idx = tid + p * 256;
        int k = idx >> 4, q = idx & 15;
        *(float4*)&Ws[k * 64 + 4 * q] = *(const float4*)&g_W[k * JCOLS + 4 * q];
    }
    __syncthreads();

    const int tx = tid & 15, ty = tid >> 4;
    float rs[4] = {0.f, 0.f, 0.f, 0.f};
    float yout[4][4];

    for (int ch = 0; ch < 15; ch++) {
        // prefetch next W chunk into registers
        float4 pref[4];
        if (ch < 14) {
            #pragma unroll
            for (int p = 0; p < 4; p++) {
                int idx = tid + p * 256;
                int k = idx >> 4, q = idx & 15;
                pref[p] = *(const float4*)&g_W[k * JCOLS + (ch + 1) * 64 + 4 * q];
            }
        }
        // init accumulators with bias pairs {c(4tx),c(4tx+1)}, {c(4tx+2),c(4tx+3)}
        unsigned long long acc[4][2];
        {
            ulonglong2 cc = *(const ulonglong2*)&g_c[ch * 64 + 4 * tx];
            #pragma unroll
            for (int r = 0; r < 4; r++) { acc[r][0] = cc.x; acc[r][1] = cc.y; }
        }
        #pragma unroll
        for (int k = 0; k < 64; k++) {
            ulonglong2 ad01 = *(ulonglong2*)&Xsdup[k * 128 + 8 * ty];      // {x_m0,x_m0},{x_m1,x_m1}
            ulonglong2 ad23 = *(ulonglong2*)&Xsdup[k * 128 + 8 * ty + 4];  // {x_m2,x_m2},{x_m3,x_m3}
            ulonglong2 bv   = *(ulonglong2*)&Ws[k * 64 + 4 * tx];          // {w0,w1},{w2,w3}
            asm("fma.rn.f32x2 %0, %1, %2, %0;" : "+l"(acc[0][0]) : "l"(ad01.x), "l"(bv.x));
            asm("fma.rn.f32x2 %0, %1, %2, %0;" : "+l"(acc[0][1]) : "l"(ad01.x), "l"(bv.y));
            asm("fma.rn.f32x2 %0, %1, %2, %0;" : "+l"(acc[1][0]) : "l"(ad01.y), "l"(bv.x));
            asm("fma.rn.f32x2 %0, %1, %2, %0;" : "+l"(acc[1][1]) : "l"(ad01.y), "l"(bv.y));
            asm("fma.rn.f32x2 %0, %1, %2, %0;" : "+l"(acc[2][0]) : "l"(ad23.x), "l"(bv.x));
            asm("fma.rn.f32x2 %0, %1, %2, %0;" : "+l"(acc[2][1]) : "l"(ad23.x), "l"(bv.y));
            asm("fma.rn.f32x2 %0, %1, %2, %0;" : "+l"(acc[3][0]) : "l"(ad23.y), "l"(bv.x));
            asm("fma.rn.f32x2 %0, %1, %2, %0;" : "+l"(acc[3][1]) : "l"(ad23.y), "l"(bv.y));
        }
        // epilogue: relu + rowsum (+ stash first chunk = output cols)
        #pragma unroll
        for (int r = 0; r < 4; r++) {
            #pragma unroll
            for (int cp = 0; cp < 2; cp++) {
                float2 f = *(float2*)&acc[r][cp];
                float y0 = fmaxf(f.x, 0.0f);
                float y1 = fmaxf(f.y, 0.0f);
                rs[r] += y0 + y1;
                if (ch == 0) {
                    yout[r][2 * cp + 0] = y0;
                    yout[r][2 * cp + 1] = y1;
                }
            }
        }
        if (ch < 14) {
            __syncthreads();
            #pragma unroll
            for (int p = 0; p < 4; p++) {
                int idx = tid + p * 256;
                int k = idx >> 4, q = idx & 15;
                *(float4*)&Ws[k * 64 + 4 * q] = pref[p];
            }
            __syncthreads();
        }
    }

    // reduce row sums across the 16 tx lanes (xor<16 stays within half-warp = same ty)
    #pragma unroll
    for (int r = 0; r < 4; r++) {
        #pragma unroll
        for (int o = 1; o < 16; o <<= 1)
            rs[r] += __shfl_xor_sync(0xffffffffu, rs[r], o);
    }
    // normalize + store output (chunk-0 cols == global j 64..127 == outputs)
    #pragma unroll
    for (int r = 0; r < 4; r++) {
        float s = rs[r];
        float inv = (s > 0.0f) ? (1.0f / s) : 1.0f;
        float4 o4 = make_float4(yout[r][0] * inv, yout[r][1] * inv,
                                yout[r][2] * inv, yout[r][3] * inv);
        *(float4*)&out[(b0 + 4 * ty + r) * NO + 4 * tx] = o4;
    }
}

// ---------------- launch ---------------------------------------------------
extern "C" void kernel_launch(void* const* d_in, const int* in_sizes, int n_in,
                              void* d_out, int out_size) {
    const float* X     = (const float*)d_in[0];  // (16384, 64)
    const float* ident = (const float*)d_in[1];  // (1024,)
    const float* enh   = (const float*)d_in[2];  // (1024,)
    const float* inh   = (const float*)d_in[3];  // (1024,)
    const float* beta  = (const float*)d_in[4];  // (1,)
    const float* delta = (const float*)d_in[5];  // (1,)
    (void)in_sizes; (void)n_in; (void)out_size;

    kprep<<<JCOLS, 256>>>(ident, enh, inh, beta, delta);
    kwarm<<<WBLK, 512>>>(delta);
    kmain<<<NB / 64, 256>>>(X, (float*)d_out);
}

// round 4
// speedup vs baseline: 2.0606x; 1.4423x over previous
#include <cuda_runtime.h>
#include <cuda_bf16.h>

// Problem constants
#define NI 64
#define NO 64
#define NN 1024
#define NB 16384
#define NWARM 25
#define JCOLS 960   // j in [64,1024)
#define WK 896      // regulator rows k in [128,1024)

// ---------------- device scratch (no allocations allowed) ----------------
__device__ float g_W[NI * JCOLS];   // (delta/N) * S[k][64+n], k<64
__device__ float g_cs0[JCOLS];      // (1/N) * sum_{k<64} S[k][j]
__device__ float g_c[JCOLS];        // bias c[n] for batch step
// factorization tables (written by kprep, read by kwarm)
__device__ float g_sWe[WK], g_sVe[WK];   // sorted-by-enh: e^{+b u}, e^{-b u}
__device__ float g_sWi[WK], g_sVi[WK];   // sorted-by-inh
__device__ int   g_Ge[WK], g_Gi[WK];     // gather: c-array index (k-64)
__device__ int   g_Pe[JCOLS], g_Pi[JCOLS];   // split pos per j
__device__ float g_E1[JCOLS], g_E2[JCOLS];   // e^{-b id_j}, e^{+b id_j}

// ---------------- kernel A: W row + colsum + factorization tables --------
// grid = 960 blocks (j = 64 + bid), 256 threads
__global__ void __launch_bounds__(256) kprep(const float* __restrict__ ident,
                      const float* __restrict__ enh,
                      const float* __restrict__ inh,
                      const float* __restrict__ beta,
                      const float* __restrict__ delta) {
    const int bid = blockIdx.x, tid = threadIdx.x;
    const int lane = tid & 31, wid = tid >> 5;
    const float b = beta[0];
    const float sc = delta[0] * (1.0f / (float)NN);
    const float y = ident[NI + bid];

    // ---- W row (k<64) + column sum ----
    __shared__ float wred[2];
    float v = 0.0f;
    if (tid < 64) {
        float e = __expf(-b * fabsf(enh[tid] - y));
        float h = __expf(-b * fabsf(inh[tid] - y));
        v = e - h;
        g_W[tid * JCOLS + bid] = v * sc;
    }
    {
        float r = v;
        #pragma unroll
        for (int o = 16; o > 0; o >>= 1) r += __shfl_xor_sync(0xffffffffu, r, o);
        if (lane == 0 && wid < 2) wred[wid] = r;
    }

    // ---- counts: pos (this j) and ranks (element bid, if bid<WK) ----
    const bool doRank = (bid < WK);
    float ue = 0.f, ui = 0.f;
    if (doRank) { ue = enh[128 + bid]; ui = inh[128 + bid]; }
    int cE = 0, cI = 0, rE = 0, rI = 0;
    for (int m = tid; m < WK; m += 256) {
        float ae = enh[128 + m], ai = inh[128 + m];
        cE += (ae < y);
        cI += (ai < y);
        if (doRank) {
            rE += (ae < ue) || (ae == ue && m < bid);
            rI += (ai < ui) || (ai == ui && m < bid);
        }
    }
    __shared__ int red4[8][4];
    {
        #pragma unroll
        for (int o = 16; o > 0; o >>= 1) {
            cE += __shfl_xor_sync(0xffffffffu, cE, o);
            cI += __shfl_xor_sync(0xffffffffu, cI, o);
            rE += __shfl_xor_sync(0xffffffffu, rE, o);
            rI += __shfl_xor_sync(0xffffffffu, rI, o);
        }
        if (lane == 0) { red4[wid][0]=cE; red4[wid][1]=cI; red4[wid][2]=rE; red4[wid][3]=rI; }
    }
    __syncthreads();
    if (tid == 0) {
        int CE=0, CI=0, RE=0, RI=0;
        #pragma unroll
        for (int w = 0; w < 8; w++) { CE+=red4[w][0]; CI+=red4[w][1]; RE+=red4[w][2]; RI+=red4[w][3]; }
        g_Pe[bid] = CE;
        g_Pi[bid] = CI;
        g_cs0[bid] = (wred[0] + wred[1]) * (1.0f / (float)NN);
        g_E1[bid] = __expf(-b * y);
        g_E2[bid] = __expf( b * y);
        if (doRank) {
            g_sWe[RE] = __expf( b * ue);
            g_sVe[RE] = __expf(-b * ue);
            g_Ge[RE]  = 64 + bid;          // c-array index of k = 128+bid
            g_sWi[RI] = __expf( b * ui);
            g_sVi[RI] = __expf(-b * ui);
            g_Gi[RI]  = 64 + bid;
        }
    }
}

// ---------------- kernel B: warmup, single block, prefix-scan matvec -----
struct WarmSmem {
    float We[WK], Ve[WK], Wi[WK], Vi[WK];
    int   Ge[WK], Gi[WK];
    int   Pe[JCOLS], Pi[JCOLS];
    float E1[JCOLS], E2[JCOLS], Cs0[JCOLS];
    float4 p4[WK + 1];       // exclusive prefix sums, p4[i] = sum of first i
    float cbuf[2][JCOLS];    // ping-pong unnormalized conc (j>=64)
    float4 wTot[32];
    float4 wOff[32];
    float warpS[32];
    float sS;
};

__device__ __forceinline__ float4 wscan_incl(float4 v, int lane) {
    #pragma unroll
    for (int o = 1; o < 32; o <<= 1) {
        float x = __shfl_up_sync(0xffffffffu, v.x, o);
        float y = __shfl_up_sync(0xffffffffu, v.y, o);
        float z = __shfl_up_sync(0xffffffffu, v.z, o);
        float w = __shfl_up_sync(0xffffffffu, v.w, o);
        if (lane >= o) { v.x += x; v.y += y; v.z += z; v.w += w; }
    }
    return v;
}

__global__ void __launch_bounds__(1024) kwarm(const float* __restrict__ delta) {
    extern __shared__ float _smemraw[];
    WarmSmem* S = (WarmSmem*)_smemraw;
    const int tid = threadIdx.x, lane = tid & 31, wid = tid >> 5;
    const float dscale = delta[0] * (1.0f / (float)NN);

    // load tables once
    for (int i = tid; i < WK; i += 1024) {
        S->We[i] = g_sWe[i]; S->Ve[i] = g_sVe[i];
        S->Wi[i] = g_sWi[i]; S->Vi[i] = g_sVi[i];
        S->Ge[i] = g_Ge[i];  S->Gi[i] = g_Gi[i];
    }
    for (int i = tid; i < JCOLS; i += 1024) {
        S->Pe[i] = g_Pe[i]; S->Pi[i] = g_Pi[i];
        S->E1[i] = g_E1[i]; S->E2[i] = g_E2[i];
        S->Cs0[i] = g_cs0[i];
        S->cbuf[0][i] = 1.0f / (float)NN;
    }
    if (tid == 0) S->p4[0] = make_float4(0.f, 0.f, 0.f, 0.f);
    __syncthreads();

    int cur = 0;
    float s = 1.0f;
    for (int t = 0; t <= NWARM; t++) {
        float inv = (s > 0.0f) ? (1.0f / s) : 1.0f;

        // build a/b terms + warp-inclusive scan
        float4 v = make_float4(0.f, 0.f, 0.f, 0.f);
        if (tid < WK) {
            float ce = S->cbuf[cur][S->Ge[tid]];
            float ci = S->cbuf[cur][S->Gi[tid]];
            v = make_float4(ce * S->We[tid], ce * S->Ve[tid],
                            ci * S->Wi[tid], ci * S->Vi[tid]);
        }
        float4 incl = wscan_incl(v, lane);
        if (lane == 31) S->wTot[wid] = incl;
        __syncthreads();
        if (wid == 0) {
            float4 tv = (lane < 28) ? S->wTot[lane] : make_float4(0.f,0.f,0.f,0.f);
            float4 ti = wscan_incl(tv, lane);
            S->wOff[lane] = make_float4(ti.x - tv.x, ti.y - tv.y, ti.z - tv.z, ti.w - tv.w);
        }
        __syncthreads();
        if (tid < WK) {
            float4 off = S->wOff[wid];
            S->p4[tid + 1] = make_float4(incl.x + off.x, incl.y + off.y,
                                         incl.z + off.z, incl.w + off.w);
        }
        __syncthreads();

        // evaluate all 960 columns
        float4 grand = S->p4[WK];
        float mys = 0.0f;
        if (tid < JCOLS) {
            int pe = S->Pe[tid], pi = S->Pi[tid];
            float4 fe = S->p4[pe];
            float4 fi = S->p4[pi];
            float acc = S->E1[tid] * (fe.x - fi.z)
                      + S->E2[tid] * ((fi.w - fe.y) + (grand.y - grand.w));
            float base = S->cbuf[cur][tid] * inv;
            if (t < NWARM) {
                float nv = fmaxf(base + dscale * (S->Cs0[tid] + inv * acc), 0.0f);
                S->cbuf[cur ^ 1][tid] = nv;
                mys = nv;
            } else {
                g_c[tid] = base + dscale * (inv * acc);   // bias for batch step
            }
        }
        if (t == NWARM) break;

        // reduce s = sum of new values
        #pragma unroll
        for (int o = 16; o > 0; o >>= 1) mys += __shfl_xor_sync(0xffffffffu, mys, o);
        if (lane == 0) S->warpS[wid] = mys;
        __syncthreads();
        if (tid == 0) {
            float p = 0.0f;
            #pragma unroll
            for (int w = 0; w < 32; w++) p += S->warpS[w];
            S->sS = p;
        }
        __syncthreads();
        s = S->sS;
        cur ^= 1;
    }
}

// ---------------- kernel C: main batch GEMM + relu + rowsum + normalize --
// C[16384 x 960] = X[16384 x 64] * W[64 x 960] + c; relu; rowsum; out = cols 0..63 / s
__global__ void __launch_bounds__(256) kmain(const float* __restrict__ X,
                                             float* __restrict__ out) {
    __shared__ __align__(16) float Xsdup[64 * 128];  // [k][2*m] duplicated pairs (32KB)
    __shared__ __align__(16) float Ws[64 * 64];      // [k][n] natural (16KB)
    const int tid = threadIdx.x;
    const int b0 = blockIdx.x * 64;

    #pragma unroll
    for (int p = 0; p < 4; p++) {
        int idx = tid + p * 256;
        int m = idx >> 4, q = idx & 15;
        float4 v = *(const float4*)&X[(b0 + m) * NI + q * 4];
        *(float2*)&Xsdup[(4 * q + 0) * 128 + 2 * m] = make_float2(v.x, v.x);
        *(float2*)&Xsdup[(4 * q + 1) * 128 + 2 * m] = make_float2(v.y, v.y);
        *(float2*)&Xsdup[(4 * q + 2) * 128 + 2 * m] = make_float2(v.z, v.z);
        *(float2*)&Xsdup[(4 * q + 3) * 128 + 2 * m] = make_float2(v.w, v.w);
    }
    #pragma unroll
    for (int p = 0; p < 4; p++) {
        int idx = tid + p * 256;
        int k = idx >> 4, q = idx & 15;
        *(float4*)&Ws[k * 64 + 4 * q] = *(const float4*)&g_W[k * JCOLS + 4 * q];
    }
    __syncthreads();

    const int tx = tid & 15, ty = tid >> 4;
    float rs[4] = {0.f, 0.f, 0.f, 0.f};
    float yout[4][4];

    for (int ch = 0; ch < 15; ch++) {
        float4 pref[4];
        if (ch < 14) {
            #pragma unroll
            for (int p = 0; p < 4; p++) {
                int idx = tid + p * 256;
                int k = idx >> 4, q = idx & 15;
                pref[p] = *(const float4*)&g_W[k * JCOLS + (ch + 1) * 64 + 4 * q];
            }
        }
        unsigned long long acc[4][2];
        {
            ulonglong2 cc = *(const ulonglong2*)&g_c[ch * 64 + 4 * tx];
            #pragma unroll
            for (int r = 0; r < 4; r++) { acc[r][0] = cc.x; acc[r][1] = cc.y; }
        }
        #pragma unroll
        for (int k = 0; k < 64; k++) {
            ulonglong2 ad01 = *(ulonglong2*)&Xsdup[k * 128 + 8 * ty];
            ulonglong2 ad23 = *(ulonglong2*)&Xsdup[k * 128 + 8 * ty + 4];
            ulonglong2 bv   = *(ulonglong2*)&Ws[k * 64 + 4 * tx];
            asm("fma.rn.f32x2 %0, %1, %2, %0;" : "+l"(acc[0][0]) : "l"(ad01.x), "l"(bv.x));
            asm("fma.rn.f32x2 %0, %1, %2, %0;" : "+l"(acc[0][1]) : "l"(ad01.x), "l"(bv.y));
            asm("fma.rn.f32x2 %0, %1, %2, %0;" : "+l"(acc[1][0]) : "l"(ad01.y), "l"(bv.x));
            asm("fma.rn.f32x2 %0, %1, %2, %0;" : "+l"(acc[1][1]) : "l"(ad01.y), "l"(bv.y));
            asm("fma.rn.f32x2 %0, %1, %2, %0;" : "+l"(acc[2][0]) : "l"(ad23.x), "l"(bv.x));
            asm("fma.rn.f32x2 %0, %1, %2, %0;" : "+l"(acc[2][1]) : "l"(ad23.x), "l"(bv.y));
            asm("fma.rn.f32x2 %0, %1, %2, %0;" : "+l"(acc[3][0]) : "l"(ad23.y), "l"(bv.x));
            asm("fma.rn.f32x2 %0, %1, %2, %0;" : "+l"(acc[3][1]) : "l"(ad23.y), "l"(bv.y));
        }
        #pragma unroll
        for (int r = 0; r < 4; r++) {
            #pragma unroll
            for (int cp = 0; cp < 2; cp++) {
                float2 f = *(float2*)&acc[r][cp];
                float y0 = fmaxf(f.x, 0.0f);
                float y1 = fmaxf(f.y, 0.0f);
                rs[r] += y0 + y1;
                if (ch == 0) {
                    yout[r][2 * cp + 0] = y0;
                    yout[r][2 * cp + 1] = y1;
                }
            }
        }
        if (ch < 14) {
            __syncthreads();
            #pragma unroll
            for (int p = 0; p < 4; p++) {
                int idx = tid + p * 256;
                int k = idx >> 4, q = idx & 15;
                *(float4*)&Ws[k * 64 + 4 * q] = pref[p];
            }
            __syncthreads();
        }
    }

    #pragma unroll
    for (int r = 0; r < 4; r++) {
        #pragma unroll
        for (int o = 1; o < 16; o <<= 1)
            rs[r] += __shfl_xor_sync(0xffffffffu, rs[r], o);
    }
    #pragma unroll
    for (int r = 0; r < 4; r++) {
        float s = rs[r];
        float inv = (s > 0.0f) ? (1.0f / s) : 1.0f;
        float4 o4 = make_float4(yout[r][0] * inv, yout[r][1] * inv,
                                yout[r][2] * inv, yout[r][3] * inv);
        *(float4*)&out[(b0 + 4 * ty + r) * NO + 4 * tx] = o4;
    }
}

// ---------------- launch ---------------------------------------------------
extern "C" void kernel_launch(void* const* d_in, const int* in_sizes, int n_in,
                              void* d_out, int out_size) {
    const float* X     = (const float*)d_in[0];  // (16384, 64)
    const float* ident = (const float*)d_in[1];  // (1024,)
    const float* enh   = (const float*)d_in[2];  // (1024,)
    const float* inh   = (const float*)d_in[3];  // (1024,)
    const float* beta  = (const float*)d_in[4];  // (1,)
    const float* delta = (const float*)d_in[5];  // (1,)
    (void)in_sizes; (void)n_in; (void)out_size;

    cudaFuncSetAttribute(kwarm, cudaFuncAttributeMaxDynamicSharedMemorySize,
                         (int)sizeof(WarmSmem));

    kprep<<<JCOLS, 256>>>(ident, enh, inh, beta, delta);
    kwarm<<<1, 1024, sizeof(WarmSmem)>>>(delta);
    kmain<<<NB / 64, 256>>>(X, (float*)d_out);
}

// round 6
// speedup vs baseline: 2.7370x; 1.3282x over previous
#include <cuda_runtime.h>
#include <cuda_bf16.h>

// Problem constants
#define NI 64
#define NO 64
#define NN 1024
#define NB 16384
#define NWARM 25
#define JCOLS 960   // j in [64,1024)
#define WK 896      // regulator rows k in [128,1024)

// ---------------- device scratch (no allocations allowed) ----------------
__device__ float4 g_jc[JCOLS];      // per-col: {dscale*E1, dscale*E2, c, bits(qe|qi<<16)}
__device__ float g_cs0[JCOLS];      // (1/N) * sum_{k<64} S[k][j]  (for warmup)
__device__ float g_E1[JCOLS], g_E2[JCOLS];   // e^{-b id_j}, e^{+b id_j} (for warmup)
// warmup factorization tables (k>=128)
__device__ float g_sWe[WK], g_sVe[WK];
__device__ float g_sWi[WK], g_sVi[WK];
__device__ int   g_Ge[WK], g_Gi[WK];
__device__ int   g_Pe[JCOLS], g_Pi[JCOLS];
// batch factorization tables (k<64)
__device__ float g_we64[64], g_ve64[64], g_wi64[64], g_vi64[64];
__device__ int   g_bge[64], g_bgi[64];

// ---------------- kernel A: per-column constants + sort/rank tables ------
// grid = 960 blocks (j = 64 + bid), 256 threads
__global__ void __launch_bounds__(256) kprep(const float* __restrict__ ident,
                      const float* __restrict__ enh,
                      const float* __restrict__ inh,
                      const float* __restrict__ beta,
                      const float* __restrict__ delta) {
    const int bid = blockIdx.x, tid = threadIdx.x;
    const int lane = tid & 31, wid = tid >> 5;
    const float b = beta[0];
    const float dscale = delta[0] * (1.0f / (float)NN);
    const float y = ident[NI + bid];

    __shared__ float wred[2];
    __shared__ int red4[8][4];
    __shared__ int scnt[4];          // qe, qi, rank64E, rank64I
    if (tid < 4) scnt[tid] = 0;

    // ---- colsum over k<64 (for warmup cs0) ----
    float v = 0.0f;
    if (tid < 64) {
        float ev = enh[tid], iv = inh[tid];
        v = __expf(-b * fabsf(ev - y)) - __expf(-b * fabsf(iv - y));
    }
    {
        float r = v;
        #pragma unroll
        for (int o = 16; o > 0; o >>= 1) r += __shfl_xor_sync(0xffffffffu, r, o);
        if (lane == 0 && wid < 2) wred[wid] = r;
    }
    __syncthreads();   // scnt init + wred visible

    // ---- small counts/ranks over k<64 ----
    if (tid < 64) {
        float ev = enh[tid], iv = inh[tid];
        if (ev < y) atomicAdd(&scnt[0], 1);
        if (iv < y) atomicAdd(&scnt[1], 1);
        if (bid < 64) {
            float eb = enh[bid], ib2 = inh[bid];
            if (ev < eb || (ev == eb && tid < bid)) atomicAdd(&scnt[2], 1);
            if (iv < ib2 || (iv == ib2 && tid < bid)) atomicAdd(&scnt[3], 1);
        }
    }

    // ---- counts: pos (this j) and ranks (element bid, if bid<WK) over k>=128 ----
    const bool doRank = (bid < WK);
    float ue = 0.f, ui = 0.f;
    if (doRank) { ue = enh[128 + bid]; ui = inh[128 + bid]; }
    int cE = 0, cI = 0, rE = 0, rI = 0;
    for (int m = tid; m < WK; m += 256) {
        float ae = enh[128 + m], ai = inh[128 + m];
        cE += (ae < y);
        cI += (ai < y);
        if (doRank) {
            rE += (ae < ue) || (ae == ue && m < bid);
            rI += (ai < ui) || (ai == ui && m < bid);
        }
    }
    {
        #pragma unroll
        for (int o = 16; o > 0; o >>= 1) {
            cE += __shfl_xor_sync(0xffffffffu, cE, o);
            cI += __shfl_xor_sync(0xffffffffu, cI, o);
            rE += __shfl_xor_sync(0xffffffffu, rE, o);
            rI += __shfl_xor_sync(0xffffffffu, rI, o);
        }
        if (lane == 0) { red4[wid][0]=cE; red4[wid][1]=cI; red4[wid][2]=rE; red4[wid][3]=rI; }
    }
    __syncthreads();
    if (tid == 0) {
        int CE=0, CI=0, RE=0, RI=0;
        #pragma unroll
        for (int w = 0; w < 8; w++) { CE+=red4[w][0]; CI+=red4[w][1]; RE+=red4[w][2]; RI+=red4[w][3]; }
        g_Pe[bid] = CE;
        g_Pi[bid] = CI;
        g_cs0[bid] = (wred[0] + wred[1]) * (1.0f / (float)NN);
        float e1 = __expf(-b * y), e2 = __expf(b * y);
        g_E1[bid] = e1;
        g_E2[bid] = e2;
        g_jc[bid].x = dscale * e1;
        g_jc[bid].y = dscale * e2;
        g_jc[bid].w = __int_as_float(scnt[0] | (scnt[1] << 16));
        if (doRank) {
            g_sWe[RE] = __expf( b * ue);
            g_sVe[RE] = __expf(-b * ue);
            g_Ge[RE]  = 64 + bid;
            g_sWi[RI] = __expf( b * ui);
            g_sVi[RI] = __expf(-b * ui);
            g_Gi[RI]  = 64 + bid;
        }
        if (bid < 64) {
            float eb = enh[bid], ib2 = inh[bid];
            int re = scnt[2], ri = scnt[3];
            g_bge[re] = bid;
            g_we64[re] = __expf( b * eb);
            g_ve64[re] = __expf(-b * eb);
            g_bgi[ri] = bid;
            g_wi64[ri] = __expf( b * ib2);
            g_vi64[ri] = __expf(-b * ib2);
        }
    }
}

// ---------------- kernel B: warmup, single block, prefix-scan matvec -----
struct WarmSmem {
    float We[WK], Ve[WK], Wi[WK], Vi[WK];
    int   Ge[WK], Gi[WK];
    int   Pe[JCOLS], Pi[JCOLS];
    float E1[JCOLS], E2[JCOLS], Cs0[JCOLS];
    float4 p4[WK + 1];
    float cbuf[2][JCOLS];
    float4 wTot[32];
    float4 wOff[32];
    float warpS[32];
    float sS;
};

__device__ __forceinline__ float4 wscan_incl(float4 v, int lane) {
    #pragma unroll
    for (int o = 1; o < 32; o <<= 1) {
        float x = __shfl_up_sync(0xffffffffu, v.x, o);
        float y = __shfl_up_sync(0xffffffffu, v.y, o);
        float z = __shfl_up_sync(0xffffffffu, v.z, o);
        float w = __shfl_up_sync(0xffffffffu, v.w, o);
        if (lane >= o) { v.x += x; v.y += y; v.z += z; v.w += w; }
    }
    return v;
}

__global__ void __launch_bounds__(1024) kwarm(const float* __restrict__ delta) {
    extern __shared__ float _smemraw[];
    WarmSmem* S = (WarmSmem*)_smemraw;
    const int tid = threadIdx.x, lane = tid & 31, wid = tid >> 5;
    const float dscale = delta[0] * (1.0f / (float)NN);

    for (int i = tid; i < WK; i += 1024) {
        S->We[i] = g_sWe[i]; S->Ve[i] = g_sVe[i];
        S->Wi[i] = g_sWi[i]; S->Vi[i] = g_sVi[i];
        S->Ge[i] = g_Ge[i];  S->Gi[i] = g_Gi[i];
    }
    for (int i = tid; i < JCOLS; i += 1024) {
        S->Pe[i] = g_Pe[i]; S->Pi[i] = g_Pi[i];
        S->E1[i] = g_E1[i]; S->E2[i] = g_E2[i];
        S->Cs0[i] = g_cs0[i];
        S->cbuf[0][i] = 1.0f / (float)NN;
    }
    if (tid == 0) S->p4[0] = make_float4(0.f, 0.f, 0.f, 0.f);
    __syncthreads();

    int cur = 0;
    float s = 1.0f;
    for (int t = 0; t <= NWARM; t++) {
        float inv = (s > 0.0f) ? (1.0f / s) : 1.0f;

        float4 v = make_float4(0.f, 0.f, 0.f, 0.f);
        if (tid < WK) {
            float ce = S->cbuf[cur][S->Ge[tid]];
            float ci = S->cbuf[cur][S->Gi[tid]];
            v = make_float4(ce * S->We[tid], ce * S->Ve[tid],
                            ci * S->Wi[tid], ci * S->Vi[tid]);
        }
        float4 incl = wscan_incl(v, lane);
        if (lane == 31) S->wTot[wid] = incl;
        __syncthreads();
        if (wid == 0) {
            float4 tv = (lane < 28) ? S->wTot[lane] : make_float4(0.f,0.f,0.f,0.f);
            float4 ti = wscan_incl(tv, lane);
            S->wOff[lane] = make_float4(ti.x - tv.x, ti.y - tv.y, ti.z - tv.z, ti.w - tv.w);
        }
        __syncthreads();
        if (tid < WK) {
            float4 off = S->wOff[wid];
            S->p4[tid + 1] = make_float4(incl.x + off.x, incl.y + off.y,
                                         incl.z + off.z, incl.w + off.w);
        }
        __syncthreads();

        float4 grand = S->p4[WK];
        float mys = 0.0f;
        if (tid < JCOLS) {
            int pe = S->Pe[tid], pi = S->Pi[tid];
            float4 fe = S->p4[pe];
            float4 fi = S->p4[pi];
            float acc = S->E1[tid] * (fe.x - fi.z)
                      + S->E2[tid] * ((fi.w - fe.y) + (grand.y - grand.w));
            float base = S->cbuf[cur][tid] * inv;
            if (t < NWARM) {
                float nv = fmaxf(base + dscale * (S->Cs0[tid] + inv * acc), 0.0f);
                S->cbuf[cur ^ 1][tid] = nv;
                mys = nv;
            } else {
                g_jc[tid].z = base + dscale * (inv * acc);   // bias for batch step
            }
        }
        if (t == NWARM) break;

        #pragma unroll
        for (int o = 16; o > 0; o >>= 1) mys += __shfl_xor_sync(0xffffffffu, mys, o);
        if (lane == 0) S->warpS[wid] = mys;
        __syncthreads();
        if (tid == 0) {
            float p = 0.0f;
            #pragma unroll
            for (int w = 0; w < 32; w++) p += S->warpS[w];
            S->sS = p;
        }
        __syncthreads();
        s = S->sS;
        cur ^= 1;
    }
}

// ---------------- kernel C: batch step via factorized kernel evaluation --
// 32 rows/block, 128 threads (4 warps, lane = row). Per row: 4 prefix tables
// over the 64 sorted inputs, then 960 columns at ~10 ops each.
struct MainSmem {
    float  Xs[64 * 32];       // [k][row]
    float2 Te[65 * 32];       // [pos][row]  (PAe, PBe)
    float2 Ti[65 * 32];       // [pos][row]  (PAi, PBi)
    float  Yout[64 * 32];     // [col][row]
    float  TBe[32], TBi[32];
    float  warpS[4][32];
    float  sInv[32];
};

__global__ void __launch_bounds__(128) kmain(const float* __restrict__ X,
                                             float* __restrict__ out) {
    extern __shared__ float _smraw[];
    MainSmem* S = (MainSmem*)_smraw;
    const int tid = threadIdx.x, lane = tid & 31, w = tid >> 5;
    const int rowbase = blockIdx.x * 32;

    // load X transposed: thread t -> row (t>>2), k-range (t&3)*16..+15
    {
        int r = tid >> 2, kq = (tid & 3) * 16;
        const float* xp = &X[(rowbase + r) * NI + kq];
        #pragma unroll
        for (int u = 0; u < 16; u += 4) {
            float4 vv = *(const float4*)&xp[u];
            S->Xs[(kq + u + 0) * 32 + r] = vv.x;
            S->Xs[(kq + u + 1) * 32 + r] = vv.y;
            S->Xs[(kq + u + 2) * 32 + r] = vv.z;
            S->Xs[(kq + u + 3) * 32 + r] = vv.w;
        }
    }
    __syncthreads();

    // build prefix tables: warp 0 -> Te, warp 1 -> Ti
    if (w < 2) {
        const int*   gp = (w == 0) ? g_bge : g_bgi;
        const float* gw = (w == 0) ? g_we64 : g_wi64;
        const float* gv = (w == 0) ? g_ve64 : g_vi64;
        float2* T = (w == 0) ? S->Te : S->Ti;
        float pa = 0.f, pb = 0.f;
        #pragma unroll 8
        for (int r = 0; r < 64; r++) {
            T[r * 32 + lane] = make_float2(pa, pb);
            float xv = S->Xs[__ldg(&gp[r]) * 32 + lane];
            pa = fmaf(xv, __ldg(&gw[r]), pa);
            pb = fmaf(xv, __ldg(&gv[r]), pb);
        }
        T[64 * 32 + lane] = make_float2(pa, pb);
        if (w == 0) S->TBe[lane] = pb; else S->TBi[lane] = pb;
    }
    __syncthreads();

    const float TBd = S->TBe[lane] - S->TBi[lane];
    float s = 0.f;
    #pragma unroll 4
    for (int j = w; j < JCOLS; j += 4) {
        float4 co = __ldg(&g_jc[j]);               // E1', E2', c, qpack
        int qp = __float_as_int(co.w);
        float2 te = S->Te[(qp & 0xffff) * 32 + lane];
        float2 ti = S->Ti[(qp >> 16) * 32 + lane];
        float A  = te.x - ti.x;
        float Bv = TBd - (te.y - ti.y);
        float z  = fmaf(co.y, Bv, fmaf(co.x, A, co.z));
        float yv = fmaxf(z, 0.f);
        s += yv;
        if (j < 64) S->Yout[j * 32 + lane] = yv;   // output cols (global j 64..127)
    }
    S->warpS[w][lane] = s;
    __syncthreads();
    if (w == 0) {
        float stot = S->warpS[0][lane] + S->warpS[1][lane]
                   + S->warpS[2][lane] + S->warpS[3][lane];
        S->sInv[lane] = (stot > 0.f) ? (1.0f / stot) : 1.0f;
    }
    __syncthreads();

    // write out: thread t -> row (t>>2), cols (t&3)*16..+15
    {
        int r = tid >> 2, c0 = (tid & 3) * 16;
        float inv = S->sInv[r];
        float* op = &out[(rowbase + r) * NO + c0];
        #pragma unroll
        for (int u = 0; u < 16; u += 4) {
            float4 vv = make_float4(S->Yout[(c0 + u + 0) * 32 + r] * inv,
                                    S->Yout[(c0 + u + 1) * 32 + r] * inv,
                                    S->Yout[(c0 + u + 2) * 32 + r] * inv,
                                    S->Yout[(c0 + u + 3) * 32 + r] * inv);
            *(float4*)&op[u] = vv;
        }
    }
}

// ---------------- launch ---------------------------------------------------
extern "C" void kernel_launch(void* const* d_in, const int* in_sizes, int n_in,
                              void* d_out, int out_size) {
    const float* X     = (const float*)d_in[0];  // (16384, 64)
    const float* ident = (const float*)d_in[1];  // (1024,)
    const float* enh   = (const float*)d_in[2];  // (1024,)
    const float* inh   = (const float*)d_in[3];  // (1024,)
    const float* beta  = (const float*)d_in[4];  // (1,)
    const float* delta = (const float*)d_in[5];  // (1,)
    (void)in_sizes; (void)n_in; (void)out_size;

    cudaFuncSetAttribute(kwarm, cudaFuncAttributeMaxDynamicSharedMemorySize,
                         (int)sizeof(WarmSmem));
    cudaFuncSetAttribute(kmain, cudaFuncAttributeMaxDynamicSharedMemorySize,
                         (int)sizeof(MainSmem));

    kprep<<<JCOLS, 256>>>(ident, enh, inh, beta, delta);
    kwarm<<<1, 1024, sizeof(WarmSmem)>>>(delta);
    kmain<<<NB / 32, 128, sizeof(MainSmem)>>>(X, (float*)d_out);
}

// round 7
// speedup vs baseline: 3.0633x; 1.1192x over previous
#include <cuda_runtime.h>
#include <cuda_bf16.h>

// Problem constants
#define NI 64
#define NO 64
#define NN 1024
#define NB 16384
#define NWARM 25
#define JCOLS 960   // j in [64,1024)
#define WK 896      // regulator rows k in [128,1024)

// ---------------- device scratch (no allocations allowed) ----------------
__device__ float4 g_jc[JCOLS];      // per-col: {dscale*E1, dscale*E2, c, bits(qe|qi<<16)}
__device__ float g_cs0[JCOLS];      // (1/N) * sum_{k<64} S[k][j]  (for warmup)
__device__ float g_E1[JCOLS], g_E2[JCOLS];   // e^{-b id_j}, e^{+b id_j}
// warmup factorization tables (k>=128), sorted order
__device__ float g_sWe[WK], g_sVe[WK];
__device__ float g_sWi[WK], g_sVi[WK];
__device__ int   g_Ge[WK], g_Gi[WK];
__device__ int   g_Pe[JCOLS], g_Pi[JCOLS];
// batch factorization tables (k<64), sorted order
__device__ float g_we64[64], g_ve64[64], g_wi64[64], g_vi64[64];
__device__ int   g_bge[64], g_bgi[64];

// ---------------- kernel A: per-column constants + sort/rank tables ------
// warp-per-column: 120 blocks x 256 threads = 960 warps
__global__ void __launch_bounds__(256) kprep(const float* __restrict__ ident,
                      const float* __restrict__ enh,
                      const float* __restrict__ inh,
                      const float* __restrict__ beta,
                      const float* __restrict__ delta) {
    const int lane = threadIdx.x & 31, wid = threadIdx.x >> 5;
    const int g = blockIdx.x * 8 + wid;          // 0..959 (column jrel & element id)
    const float b = beta[0];
    const float dscale = delta[0] * (1.0f / (float)NN);
    const float y = __ldg(&ident[NI + g]);

    const bool small = (g < 64);
    float eb = 0.f, ib = 0.f;
    if (small) { eb = __ldg(&enh[g]); ib = __ldg(&inh[g]); }

    // small part k<64: 2 elems per lane
    float cs = 0.f;
    int pack1 = 0;   // qe | qi<<8 | r64e<<16 | r64i<<24
    #pragma unroll
    for (int u = 0; u < 2; u++) {
        int k = lane + 32 * u;
        float ev = __ldg(&enh[k]), iv = __ldg(&inh[k]);
        cs += __expf(-b * fabsf(ev - y)) - __expf(-b * fabsf(iv - y));
        pack1 += (ev < y) ? 1 : 0;
        pack1 += (iv < y) ? (1 << 8) : 0;
        if (small) {
            pack1 += ((ev < eb) || (ev == eb && k < g)) ? (1 << 16) : 0;
            pack1 += ((iv < ib) || (iv == ib && k < g)) ? (1 << 24) : 0;
        }
    }

    // big part k>=128: 28 elems per lane
    const bool dorank = (g < WK);
    float ue = 0.f, ui = 0.f;
    if (dorank) { ue = __ldg(&enh[128 + g]); ui = __ldg(&inh[128 + g]); }
    int pack2 = 0;   // cE | cI<<16
    int pack3 = 0;   // rE | rI<<16
    #pragma unroll 7
    for (int m = lane; m < WK; m += 32) {
        float ae = __ldg(&enh[128 + m]), ai = __ldg(&inh[128 + m]);
        pack2 += (ae < y) ? 1 : 0;
        pack2 += (ai < y) ? (1 << 16) : 0;
        if (dorank) {
            pack3 += ((ae < ue) || (ae == ue && m < g)) ? 1 : 0;
            pack3 += ((ai < ui) || (ai == ui && m < g)) ? (1 << 16) : 0;
        }
    }
    #pragma unroll
    for (int o = 16; o > 0; o >>= 1) {
        cs    += __shfl_xor_sync(0xffffffffu, cs, o);
        pack1 += __shfl_xor_sync(0xffffffffu, pack1, o);
        pack2 += __shfl_xor_sync(0xffffffffu, pack2, o);
        pack3 += __shfl_xor_sync(0xffffffffu, pack3, o);
    }
    if (lane == 0) {
        int qe = pack1 & 0xff, qi = (pack1 >> 8) & 0xff;
        int r64e = (pack1 >> 16) & 0xff, r64i = (pack1 >> 24) & 0xff;
        int cE = pack2 & 0xffff, cI = pack2 >> 16;
        int rE = pack3 & 0xffff, rI = pack3 >> 16;
        g_Pe[g] = cE;
        g_Pi[g] = cI;
        g_cs0[g] = cs * (1.0f / (float)NN);
        float e1 = __expf(-b * y), e2 = __expf(b * y);
        g_E1[g] = e1;
        g_E2[g] = e2;
        float4 jc;
        jc.x = dscale * e1;
        jc.y = dscale * e2;
        jc.z = 0.0f;                         // filled by kwarm
        jc.w = __int_as_float(qe | (qi << 16));
        g_jc[g] = jc;
        if (dorank) {
            g_sWe[rE] = __expf( b * ue);
            g_sVe[rE] = __expf(-b * ue);
            g_Ge[rE]  = 64 + g;
            g_sWi[rI] = __expf( b * ui);
            g_sVi[rI] = __expf(-b * ui);
            g_Gi[rI]  = 64 + g;
        }
        if (small) {
            g_bge[r64e] = g;
            g_we64[r64e] = __expf( b * eb);
            g_ve64[r64e] = __expf(-b * eb);
            g_bgi[r64i] = g;
            g_wi64[r64i] = __expf( b * ib);
            g_vi64[r64i] = __expf(-b * ib);
        }
    }
}

// ---------------- kernel B: warmup, single block of 256, reg-resident ----
// 224 scan-active threads x 4 sorted elements; all tables in registers.
__global__ void __launch_bounds__(256) kwarm(const float* __restrict__ delta) {
    __shared__ __align__(16) float4 p4[WK + 1];   // exclusive prefixes {Ae,Be,Ai,Bi}
    __shared__ float cbuf[2][JCOLS];
    __shared__ float4 wTot[8], wOff[8];
    __shared__ float warpS[8];

    const int tid = threadIdx.x, lane = tid & 31, wid = tid >> 5;
    const float dscale = delta[0] * (1.0f / (float)NN);
    const bool act = (tid < 224);                 // warps 0..6 scan

    // iteration-invariant tables -> registers
    float We4[4], Ve4[4], Wi4[4], Vi4[4];
    int   Ge4[4], Gi4[4];
    if (act) {
        #pragma unroll
        for (int u = 0; u < 4; u++) {
            int e = tid * 4 + u;
            We4[u] = g_sWe[e]; Ve4[u] = g_sVe[e];
            Wi4[u] = g_sWi[e]; Vi4[u] = g_sVi[e];
            Ge4[u] = g_Ge[e];  Gi4[u] = g_Gi[e];
        }
    }
    int   pe[4], pi[4];
    float E1c[4], E2c[4], cs0c[4];
    #pragma unroll
    for (int q = 0; q < 4; q++) {
        int j = tid + 256 * q;
        if (j < JCOLS) {
            pe[q] = g_Pe[j]; pi[q] = g_Pi[j];
            E1c[q] = g_E1[j]; E2c[q] = g_E2[j]; cs0c[q] = g_cs0[j];
        }
    }
    for (int i = tid; i < JCOLS; i += 256) cbuf[0][i] = 1.0f / (float)NN;
    __syncthreads();

    int cur = 0;
    float s = 1.0f;
    for (int t = 0; t <= NWARM; t++) {
        float inv = (s > 0.0f) ? (1.0f / s) : 1.0f;

        // local exclusive prefix over this thread's 4 elements
        float ae[4], be[4], ai2[4], bi2[4];
        float4 tot = make_float4(0.f, 0.f, 0.f, 0.f);
        if (act) {
            float pa = 0.f, pb = 0.f, pc = 0.f, pd = 0.f;
            #pragma unroll
            for (int u = 0; u < 4; u++) {
                ae[u] = pa; be[u] = pb; ai2[u] = pc; bi2[u] = pd;
                float ce = cbuf[cur][Ge4[u]];
                float ci = cbuf[cur][Gi4[u]];
                pa = fmaf(ce, We4[u], pa);
                pb = fmaf(ce, Ve4[u], pb);
                pc = fmaf(ci, Wi4[u], pc);
                pd = fmaf(ci, Vi4[u], pd);
            }
            tot = make_float4(pa, pb, pc, pd);
        }
        // warp inclusive scan over thread totals
        float4 incl = tot;
        #pragma unroll
        for (int o = 1; o < 32; o <<= 1) {
            float x = __shfl_up_sync(0xffffffffu, incl.x, o);
            float y = __shfl_up_sync(0xffffffffu, incl.y, o);
            float z = __shfl_up_sync(0xffffffffu, incl.z, o);
            float w = __shfl_up_sync(0xffffffffu, incl.w, o);
            if (lane >= o) { incl.x += x; incl.y += y; incl.z += z; incl.w += w; }
        }
        if (act && lane == 31) wTot[wid] = incl;
        __syncthreads();
        if (tid < 8) {                             // scan 7 warp totals (lanes 0..7 of warp 0)
            float4 tv = (tid < 7) ? wTot[tid] : make_float4(0.f, 0.f, 0.f, 0.f);
            float4 ti = tv;
            #pragma unroll
            for (int o = 1; o < 8; o <<= 1) {
                float x = __shfl_up_sync(0x000000ffu, ti.x, o);
                float y = __shfl_up_sync(0x000000ffu, ti.y, o);
                float z = __shfl_up_sync(0x000000ffu, ti.z, o);
                float w = __shfl_up_sync(0x000000ffu, ti.w, o);
                if (lane >= o) { ti.x += x; ti.y += y; ti.z += z; ti.w += w; }
            }
            wOff[tid] = make_float4(ti.x - tv.x, ti.y - tv.y, ti.z - tv.z, ti.w - tv.w);
        }
        __syncthreads();
        if (act) {
            float4 off = wOff[wid];
            float ex0 = (incl.x - tot.x) + off.x;
            float ex1 = (incl.y - tot.y) + off.y;
            float ex2 = (incl.z - tot.z) + off.z;
            float ex3 = (incl.w - tot.w) + off.w;
            #pragma unroll
            for (int u = 0; u < 4; u++)
                p4[tid * 4 + u] = make_float4(ex0 + ae[u], ex1 + be[u],
                                              ex2 + ai2[u], ex3 + bi2[u]);
            if (tid == 223)
                p4[WK] = make_float4(ex0 + tot.x, ex1 + tot.y,
                                     ex2 + tot.z, ex3 + tot.w);
        }
        __syncthreads();

        float4 grand = p4[WK];
        float mys = 0.0f;
        #pragma unroll
        for (int q = 0; q < 4; q++) {
            int j = tid + 256 * q;
            if (j < JCOLS) {
                float4 fe = p4[pe[q]];
                float4 fi = p4[pi[q]];
                float acc = E1c[q] * (fe.x - fi.z)
                          + E2c[q] * ((fi.w - fe.y) + (grand.y - grand.w));
                float base = cbuf[cur][j] * inv;
                if (t < NWARM) {
                    float nv = fmaxf(base + dscale * (cs0c[q] + inv * acc), 0.0f);
                    cbuf[cur ^ 1][j] = nv;
                    mys += nv;
                } else {
                    g_jc[j].z = base + dscale * (inv * acc);   // bias for batch step
                }
            }
        }
        if (t == NWARM) break;

        #pragma unroll
        for (int o = 16; o > 0; o >>= 1) mys += __shfl_xor_sync(0xffffffffu, mys, o);
        if (lane == 0) warpS[wid] = mys;
        __syncthreads();
        s = ((warpS[0] + warpS[1]) + (warpS[2] + warpS[3]))
          + ((warpS[4] + warpS[5]) + (warpS[6] + warpS[7]));
        cur ^= 1;
    }
}

// ---------------- kernel C: batch step via factorized kernel evaluation --
struct MainSmem {
    float  Xs[64 * 32];       // [k][row]
    float2 Te[65 * 32];       // [pos][row]  (PAe, PBe)
    float2 Ti[65 * 32];       // [pos][row]  (PAi, PBi)
    float  Yout[64 * 32];     // [col][row]
    float  TBe[32], TBi[32];
    float  warpS[4][32];
    float  sInv[32];
};

__global__ void __launch_bounds__(128) kmain(const float* __restrict__ X,
                                             float* __restrict__ out) {
    extern __shared__ float _smraw[];
    MainSmem* S = (MainSmem*)_smraw;
    const int tid = threadIdx.x, lane = tid & 31, w = tid >> 5;
    const int rowbase = blockIdx.x * 32;

    {
        int r = tid >> 2, kq = (tid & 3) * 16;
        const float* xp = &X[(rowbase + r) * NI + kq];
        #pragma unroll
        for (int u = 0; u < 16; u += 4) {
            float4 vv = *(const float4*)&xp[u];
            S->Xs[(kq + u + 0) * 32 + r] = vv.x;
            S->Xs[(kq + u + 1) * 32 + r] = vv.y;
            S->Xs[(kq + u + 2) * 32 + r] = vv.z;
            S->Xs[(kq + u + 3) * 32 + r] = vv.w;
        }
    }
    __syncthreads();

    if (w < 2) {
        const int*   gp = (w == 0) ? g_bge : g_bgi;
        const float* gw = (w == 0) ? g_we64 : g_wi64;
        const float* gv = (w == 0) ? g_ve64 : g_vi64;
        float2* T = (w == 0) ? S->Te : S->Ti;
        float pa = 0.f, pb = 0.f;
        #pragma unroll 8
        for (int r = 0; r < 64; r++) {
            T[r * 32 + lane] = make_float2(pa, pb);
            float xv = S->Xs[__ldg(&gp[r]) * 32 + lane];
            pa = fmaf(xv, __ldg(&gw[r]), pa);
            pb = fmaf(xv, __ldg(&gv[r]), pb);
        }
        T[64 * 32 + lane] = make_float2(pa, pb);
        if (w == 0) S->TBe[lane] = pb; else S->TBi[lane] = pb;
    }
    __syncthreads();

    const float TBd = S->TBe[lane] - S->TBi[lane];
    float s = 0.f;
    #pragma unroll 4
    for (int j = w; j < JCOLS; j += 4) {
        float4 co = __ldg(&g_jc[j]);
        int qp = __float_as_int(co.w);
        float2 te = S->Te[(qp & 0xffff) * 32 + lane];
        float2 ti = S->Ti[(qp >> 16) * 32 + lane];
        float A  = te.x - ti.x;
        float Bv = TBd - (te.y - ti.y);
        float z  = fmaf(co.y, Bv, fmaf(co.x, A, co.z));
        float yv = fmaxf(z, 0.f);
        s += yv;
        if (j < 64) S->Yout[j * 32 + lane] = yv;
    }
    S->warpS[w][lane] = s;
    __syncthreads();
    if (w == 0) {
        float stot = S->warpS[0][lane] + S->warpS[1][lane]
                   + S->warpS[2][lane] + S->warpS[3][lane];
        S->sInv[lane] = (stot > 0.f) ? (1.0f / stot) : 1.0f;
    }
    __syncthreads();

    {
        int r = tid >> 2, c0 = (tid & 3) * 16;
        float inv = S->sInv[r];
        float* op = &out[(rowbase + r) * NO + c0];
        #pragma unroll
        for (int u = 0; u < 16; u += 4) {
            float4 vv = make_float4(S->Yout[(c0 + u + 0) * 32 + r] * inv,
                                    S->Yout[(c0 + u + 1) * 32 + r] * inv,
                                    S->Yout[(c0 + u + 2) * 32 + r] * inv,
                                    S->Yout[(c0 + u + 3) * 32 + r] * inv);
            *(float4*)&op[u] = vv;
        }
    }
}

// ---------------- launch ---------------------------------------------------
extern "C" void kernel_launch(void* const* d_in, const int* in_sizes, int n_in,
                              void* d_out, int out_size) {
    const float* X     = (const float*)d_in[0];  // (16384, 64)
    const float* ident = (const float*)d_in[1];  // (1024,)
    const float* enh   = (const float*)d_in[2];  // (1024,)
    const float* inh   = (const float*)d_in[3];  // (1024,)
    const float* beta  = (const float*)d_in[4];  // (1,)
    const float* delta = (const float*)d_in[5];  // (1,)
    (void)in_sizes; (void)n_in; (void)out_size;

    cudaFuncSetAttribute(kmain, cudaFuncAttributeMaxDynamicSharedMemorySize,
                         (int)sizeof(MainSmem));

    kprep<<<120, 256>>>(ident, enh, inh, beta, delta);
    kwarm<<<1, 256>>>(delta);
    kmain<<<NB / 32, 128, sizeof(MainSmem)>>>(X, (float*)d_out);
}

// round 10
// speedup vs baseline: 3.2235x; 1.0523x over previous
#include <cuda_runtime.h>
#include <cuda_bf16.h>

// Problem constants
#define NI 64
#define NO 64
#define NN 1024
#define NB 16384
#define NWARM 25
#define JCOLS 960   // j in [64,1024)
#define WK 896      // regulator rows k in [128,1024)

// ---------------- device scratch (no allocations allowed) ----------------
__device__ float4 g_jc[JCOLS];      // per-col: {dscale*E1, dscale*E2, c, bits(qe|qi<<16)}
__device__ float g_cs0[JCOLS];      // (1/N) * sum_{k<64} S[k][j]  (for warmup)
__device__ float g_E1[JCOLS], g_E2[JCOLS];   // e^{-b id_j}, e^{+b id_j}
// warmup factorization tables (k>=128), sorted order
__device__ float g_sWe[WK], g_sVe[WK];
__device__ float g_sWi[WK], g_sVi[WK];
__device__ int   g_Ge[WK], g_Gi[WK];
__device__ int   g_Pe[JCOLS], g_Pi[JCOLS];
// batch factorization tables (k<64), sorted order
__device__ float g_we64[64], g_ve64[64], g_wi64[64], g_vi64[64];
__device__ int   g_bge[64], g_bgi[64];

// ---------------- kernel A: per-column constants + sort/rank tables ------
// block-per-column: 960 blocks x 128 threads
__global__ void __launch_bounds__(128) kprep(const float* __restrict__ ident,
                      const float* __restrict__ enh,
                      const float* __restrict__ inh,
                      const float* __restrict__ beta,
                      const float* __restrict__ delta) {
    const int g = blockIdx.x;                    // 0..959 (column jrel & element id)
    const int tid = threadIdx.x, lane = tid & 31, wid = tid >> 5;
    const float b = beta[0];
    const float dscale = delta[0] * (1.0f / (float)NN);
    const float y = __ldg(&ident[NI + g]);

    const bool small = (g < 64);
    float eb = 0.f, ib = 0.f;
    if (small) { eb = __ldg(&enh[g]); ib = __ldg(&inh[g]); }

    // small part k<64: threads 0..63, one k each
    float cs = 0.f;
    int p1 = 0;   // qe | qi<<8 | r64e<<16 | r64i<<24
    if (tid < 64) {
        float ev = __ldg(&enh[tid]), iv = __ldg(&inh[tid]);
        cs = __expf(-b * fabsf(ev - y)) - __expf(-b * fabsf(iv - y));
        p1  = (ev < y) ? 1 : 0;
        p1 += (iv < y) ? (1 << 8) : 0;
        if (small) {
            p1 += ((ev < eb) || (ev == eb && tid < g)) ? (1 << 16) : 0;
            p1 += ((iv < ib) || (iv == ib && tid < g)) ? (1 << 24) : 0;
        }
    }

    // big part k>=128: 7 elems per thread
    const bool dorank = (g < WK);
    float ue = 0.f, ui = 0.f;
    if (dorank) { ue = __ldg(&enh[128 + g]); ui = __ldg(&inh[128 + g]); }
    int p2 = 0;   // cE | cI<<16
    int p3 = 0;   // rE | rI<<16
    #pragma unroll 7
    for (int m = tid; m < WK; m += 128) {
        float ae = __ldg(&enh[128 + m]), ai = __ldg(&inh[128 + m]);
        p2 += ((ae < y) ? 1 : 0) + ((ai < y) ? (1 << 16) : 0);
        if (dorank) {
            p3 += (((ae < ue) || (ae == ue && m < g)) ? 1 : 0)
                + (((ai < ui) || (ai == ui && m < g)) ? (1 << 16) : 0);
        }
    }

    #pragma unroll
    for (int o = 16; o > 0; o >>= 1) {
        cs += __shfl_xor_sync(0xffffffffu, cs, o);
        p1 += __shfl_xor_sync(0xffffffffu, p1, o);
        p2 += __shfl_xor_sync(0xffffffffu, p2, o);
        p3 += __shfl_xor_sync(0xffffffffu, p3, o);
    }
    __shared__ float scs[4];
    __shared__ int s1[4], s2[4], s3[4];
    if (lane == 0) { scs[wid] = cs; s1[wid] = p1; s2[wid] = p2; s3[wid] = p3; }
    __syncthreads();
    if (tid == 0) {
        float CS = (scs[0] + scs[1]) + (scs[2] + scs[3]);
        int P1 = s1[0] + s1[1] + s1[2] + s1[3];
        int P2 = s2[0] + s2[1] + s2[2] + s2[3];
        int P3 = s3[0] + s3[1] + s3[2] + s3[3];
        int qe = P1 & 0xff, qi = (P1 >> 8) & 0xff;
        int r64e = (P1 >> 16) & 0xff, r64i = (P1 >> 24) & 0xff;
        int cE = P2 & 0xffff, cI = P2 >> 16;
        int rE = P3 & 0xffff, rI = P3 >> 16;
        g_Pe[g] = cE;
        g_Pi[g] = cI;
        g_cs0[g] = CS * (1.0f / (float)NN);
        float e1 = __expf(-b * y), e2 = __expf(b * y);
        g_E1[g] = e1;
        g_E2[g] = e2;
        float4 jc;
        jc.x = dscale * e1;
        jc.y = dscale * e2;
        jc.z = 0.0f;                         // filled by kwarm
        jc.w = __int_as_float(qe | (qi << 16));
        g_jc[g] = jc;
        if (dorank) {
            g_sWe[rE] = __expf( b * ue);
            g_sVe[rE] = __expf(-b * ue);
            g_Ge[rE]  = 64 + g;
            g_sWi[rI] = __expf( b * ui);
            g_sVi[rI] = __expf(-b * ui);
            g_Gi[rI]  = 64 + g;
        }
        if (small) {
            g_bge[r64e] = g;
            g_we64[r64e] = __expf( b * eb);
            g_ve64[r64e] = __expf(-b * eb);
            g_bgi[r64i] = g;
            g_wi64[r64i] = __expf( b * ib);
            g_vi64[r64i] = __expf(-b * ib);
        }
    }
}

// ---------------- kernel B: warmup, 128 threads, 4 specialized warps -----
// warps 0,1: enhancer channels (elements [0,448),[448,896)); warps 2,3: inhibitor.
// Each lane owns 14 consecutive sorted elements; tables in registers.
__global__ void __launch_bounds__(128) kwarm(const float* __restrict__ delta) {
    __shared__ __align__(16) float4 p4[WK + 1];   // exclusive prefixes {Ae,Be,Ai,Bi}
    __shared__ float cbuf[2][JCOLS];
    __shared__ float2 wTot[4];
    __shared__ float warpS[4];

    const int tid = threadIdx.x, lane = tid & 31, wid = tid >> 5;
    const float dscale = delta[0] * (1.0f / (float)NN);
    const bool isE = (wid < 2);
    const int base = (wid & 1) * 448 + lane * 14;

    // iteration-invariant tables -> registers
    float Wt[14], Vt[14];
    int   idx[14];
    {
        const float* gw = isE ? g_sWe : g_sWi;
        const float* gv = isE ? g_sVe : g_sVi;
        const int*   gi = isE ? g_Ge  : g_Gi;
        #pragma unroll
        for (int u = 0; u < 14; u++) {
            Wt[u] = __ldg(&gw[base + u]);
            Vt[u] = __ldg(&gv[base + u]);
            idx[u] = __ldg(&gi[base + u]);
        }
    }
    // per-column constants: 8 cols per thread (j = tid + 128*q)
    int   ppk[8];
    float e1r[8], e2r[8], cs0r[8];
    #pragma unroll
    for (int q = 0; q < 8; q++) {
        int j = tid + 128 * q;
        if (j < JCOLS) {
            ppk[q]  = g_Pe[j] | (g_Pi[j] << 16);
            e1r[q]  = g_E1[j];
            e2r[q]  = g_E2[j];
            cs0r[q] = g_cs0[j];
        } else {
            ppk[q] = 0; e1r[q] = 0.f; e2r[q] = 0.f; cs0r[q] = 0.f;
        }
    }
    for (int i = tid; i < JCOLS; i += 128) cbuf[0][i] = 1.0f / (float)NN;
    __syncthreads();

    int cur = 0;
    float s = 1.0f;
    for (int t = 0; t <= NWARM; t++) {
        float inv = (s > 0.0f) ? (1.0f / s) : 1.0f;

        // local exclusive prefix over 14 elements (2 channels)
        float la[14], lb[14];
        float pa = 0.f, pb = 0.f;
        #pragma unroll
        for (int u = 0; u < 14; u++) {
            la[u] = pa; lb[u] = pb;
            float c = cbuf[cur][idx[u]];
            pa = fmaf(c, Wt[u], pa);
            pb = fmaf(c, Vt[u], pb);
        }
        // warp inclusive scan of thread totals
        float ix = pa, iy = pb;
        #pragma unroll
        for (int o = 1; o < 32; o <<= 1) {
            float x = __shfl_up_sync(0xffffffffu, ix, o);
            float y = __shfl_up_sync(0xffffffffu, iy, o);
            if (lane >= o) { ix += x; iy += y; }
        }
        if (lane == 31) wTot[wid] = make_float2(ix, iy);
        __syncthreads();
        float ox = ix - pa, oy = iy - pb;            // exclusive of own total
        if (wid & 1) { ox += wTot[wid - 1].x; oy += wTot[wid - 1].y; }
        // store exclusive prefixes for this segment
        if (isE) {
            #pragma unroll
            for (int u = 0; u < 14; u++)
                *(float2*)&p4[base + u].x = make_float2(ox + la[u], oy + lb[u]);
            if (wid == 1 && lane == 31)
                *(float2*)&p4[WK].x = make_float2(ox + pa, oy + pb);
        } else {
            #pragma unroll
            for (int u = 0; u < 14; u++)
                *(float2*)&p4[base + u].z = make_float2(ox + la[u], oy + lb[u]);
            if (wid == 3 && lane == 31)
                *(float2*)&p4[WK].z = make_float2(ox + pa, oy + pb);
        }
        __syncthreads();

        float4 grand = p4[WK];
        float gterm = grand.y - grand.w;
        float mys = 0.0f;
        #pragma unroll
        for (int q = 0; q < 8; q++) {
            int j = tid + 128 * q;
            if (j < JCOLS) {
                int pe = ppk[q] & 0xffff, pi = ppk[q] >> 16;
                float4 fe = p4[pe];
                float4 fi = p4[pi];
                float acc = e1r[q] * (fe.x - fi.z)
                          + e2r[q] * ((fi.w - fe.y) + gterm);
                float bse = cbuf[cur][j] * inv;
                if (t < NWARM) {
                    float nv = fmaxf(bse + dscale * (cs0r[q] + inv * acc), 0.0f);
                    cbuf[cur ^ 1][j] = nv;
                    mys += nv;
                } else {
                    g_jc[j].z = bse + dscale * (inv * acc);   // bias for batch step
                }
            }
        }
        if (t == NWARM) break;

        #pragma unroll
        for (int o = 16; o > 0; o >>= 1) mys += __shfl_xor_sync(0xffffffffu, mys, o);
        if (lane == 0) warpS[wid] = mys;
        __syncthreads();
        s = (warpS[0] + warpS[1]) + (warpS[2] + warpS[3]);
        cur ^= 1;
    }
}

// ---------------- kernel C: batch step via factorized kernel evaluation --
struct MainSmem {
    float  Xs[64 * 32];       // [k][row]
    float2 Te[65 * 32];       // [pos][row]  (PAe, PBe)
    float2 Ti[65 * 32];       // [pos][row]  (PAi, PBi)
    float  Yout[64 * 32];     // [col][row]
    float  TBe[32], TBi[32];
    float  warpS[4][32];
    float  sInv[32];
};

__global__ void __launch_bounds__(128) kmain(const float* __restrict__ X,
                                             float* __restrict__ out) {
    extern __shared__ float _smraw[];
    MainSmem* S = (MainSmem*)_smraw;
    const int tid = threadIdx.x, lane = tid & 31, w = tid >> 5;
    const int rowbase = blockIdx.x * 32;

    {
        int r = tid >> 2, kq = (tid & 3) * 16;
        const float* xp = &X[(rowbase + r) * NI + kq];
        #pragma unroll
        for (int u = 0; u < 16; u += 4) {
            float4 vv = *(const float4*)&xp[u];
            S->Xs[(kq + u + 0) * 32 + r] = vv.x;
            S->Xs[(kq + u + 1) * 32 + r] = vv.y;
            S->Xs[(kq + u + 2) * 32 + r] = vv.z;
            S->Xs[(kq + u + 3) * 32 + r] = vv.w;
        }
    }
    __syncthreads();

    if (w < 2) {
        const int*   gp = (w == 0) ? g_bge : g_bgi;
        const float* gw = (w == 0) ? g_we64 : g_wi64;
        const float* gv = (w == 0) ? g_ve64 : g_vi64;
        float2* T = (w == 0) ? S->Te : S->Ti;
        float pa = 0.f, pb = 0.f;
        #pragma unroll 8
        for (int r = 0; r < 64; r++) {
            T[r * 32 + lane] = make_float2(pa, pb);
            float xv = S->Xs[__ldg(&gp[r]) * 32 + lane];
            pa = fmaf(xv, __ldg(&gw[r]), pa);
            pb = fmaf(xv, __ldg(&gv[r]), pb);
        }
        T[64 * 32 + lane] = make_float2(pa, pb);
        if (w == 0) S->TBe[lane] = pb; else S->TBi[lane] = pb;
    }
    __syncthreads();

    const float TBd = S->TBe[lane] - S->TBi[lane];
    float s = 0.f;
    #pragma unroll 4
    for (int j = w; j < JCOLS; j += 4) {
        float4 co = __ldg(&g_jc[j]);
        int qp = __float_as_int(co.w);
        float2 te = S->Te[(qp & 0xffff) * 32 + lane];
        float2 ti = S->Ti[(qp >> 16) * 32 + lane];
        float A  = te.x - ti.x;
        float Bv = TBd - (te.y - ti.y);
        float z  = fmaf(co.y, Bv, fmaf(co.x, A, co.z));
        float yv = fmaxf(z, 0.f);
        s += yv;
        if (j < 64) S->Yout[j * 32 + lane] = yv;
    }
    S->warpS[w][lane] = s;
    __syncthreads();
    if (w == 0) {
        float stot = S->warpS[0][lane] + S->warpS[1][lane]
                   + S->warpS[2][lane] + S->warpS[3][lane];
        S->sInv[lane] = (stot > 0.f) ? (1.0f / stot) : 1.0f;
    }
    __syncthreads();

    {
        int r = tid >> 2, c0 = (tid & 3) * 16;
        float inv = S->sInv[r];
        float* op = &out[(rowbase + r) * NO + c0];
        #pragma unroll
        for (int u = 0; u < 16; u += 4) {
            float4 vv = make_float4(S->Yout[(c0 + u + 0) * 32 + r] * inv,
                                    S->Yout[(c0 + u + 1) * 32 + r] * inv,
                                    S->Yout[(c0 + u + 2) * 32 + r] * inv,
                                    S->Yout[(c0 + u + 3) * 32 + r] * inv);
            *(float4*)&op[u] = vv;
        }
    }
}

// ---------------- launch ---------------------------------------------------
extern "C" void kernel_launch(void* const* d_in, const int* in_sizes, int n_in,
                              void* d_out, int out_size) {
    const float* X     = (const float*)d_in[0];  // (16384, 64)
    const float* ident = (const float*)d_in[1];  // (1024,)
    const float* enh   = (const float*)d_in[2];  // (1024,)
    const float* inh   = (const float*)d_in[3];  // (1024,)
    const float* beta  = (const float*)d_in[4];  // (1,)
    const float* delta = (const float*)d_in[5];  // (1,)
    (void)in_sizes; (void)n_in; (void)out_size;

    cudaFuncSetAttribute(kmain, cudaFuncAttributeMaxDynamicSharedMemorySize,
                         (int)sizeof(MainSmem));

    kprep<<<JCOLS, 128>>>(ident, enh, inh, beta, delta);
    kwarm<<<1, 128>>>(delta);
    kmain<<<NB / 32, 128, sizeof(MainSmem)>>>(X, (float*)d_out);
}